// round 15
// baseline (speedup 1.0000x reference)
#include <cuda_runtime.h>

#define BATCH 4096
#define SEQT  256
#define DIN   32
#define HID   64
#define GATES 256
#define BT    32
#define NTHR  256
#define NCTA  128
#define STK   68     // floats per k2-row of activations (64 data + 4 skew)
#define WR    512    // floats per k2-row of weights

typedef unsigned long long u64;

// ---- k-pair packed weights: Wp[k2][j][gn][c], c: (cellpar<<1)|kpar? see map below ----
// element [k2][j][gn][c]:  n = j*64 + gn*2 + (c>>1),  k = 2*k2 + (c&1)
__device__ __align__(16) float g_W0p[32 * WR];    // Whh0  (k=64 -> 32 k2-rows)
__device__ __align__(16) float g_Wx0p[16 * WR];   // Wih0  (k=32 -> 16 k2-rows, per-step LDG)
__device__ __align__(16) float g_W1p[64 * WR];    // rows 0..31 Wih1, rows 32..63 Whh1
__device__ __align__(16) float g_b0p[256];        // bias[gn*8 + q], q=(gate<<1)|cellpar
__device__ __align__(16) float g_b1p[256];

__global__ void prep_kernel(const float* __restrict__ Wih0, const float* __restrict__ Whh0,
                            const float* __restrict__ bih0, const float* __restrict__ bhh0,
                            const float* __restrict__ Wih1, const float* __restrict__ Whh1,
                            const float* __restrict__ bih1, const float* __restrict__ bhh1)
{
    int idx = blockIdx.x * blockDim.x + threadIdx.x;
    int stride = gridDim.x * blockDim.x;
    for (int i = idx; i < 32 * WR; i += stride) {
        int k2 = i >> 9, r = i & 511;
        int j = r >> 7, gn = (r >> 2) & 31, c = r & 3;
        int n = j * 64 + gn * 2 + (c >> 1);
        int k = 2 * k2 + (c & 1);
        g_W0p[i] = Whh0[n * HID + k];
    }
    for (int i = idx; i < 16 * WR; i += stride) {
        int k2 = i >> 9, r = i & 511;
        int j = r >> 7, gn = (r >> 2) & 31, c = r & 3;
        int n = j * 64 + gn * 2 + (c >> 1);
        int k = 2 * k2 + (c & 1);
        g_Wx0p[i] = Wih0[n * DIN + k];
    }
    for (int i = idx; i < 64 * WR; i += stride) {
        int k2 = i >> 9, r = i & 511;
        int j = r >> 7, gn = (r >> 2) & 31, c = r & 3;
        int n = j * 64 + gn * 2 + (c >> 1);
        int k = 2 * k2 + (c & 1);
        g_W1p[i] = (k < HID) ? Wih1[n * HID + k] : Whh1[n * HID + (k - HID)];
    }
    for (int i = idx; i < 256; i += stride) {
        int gn = i >> 3, q = i & 7;
        int n = (q >> 1) * 64 + gn * 2 + (q & 1);
        g_b0p[i] = bih0[n] + bhh0[n];
        g_b1p[i] = bih1[n] + bhh1[n];
    }
}

// ---- packed f32x2 helpers ----
__device__ __forceinline__ u64 fma2(u64 a, u64 b, u64 c) {
    u64 d;
    asm("fma.rn.f32x2 %0, %1, %2, %3;" : "=l"(d) : "l"(a), "l"(b), "l"(c));
    return d;
}
__device__ __forceinline__ u64 mul2(u64 a, u64 b) {
    u64 d;
    asm("mul.rn.f32x2 %0, %1, %2;" : "=l"(d) : "l"(a), "l"(b));
    return d;
}
__device__ __forceinline__ float2 unpack2(u64 v) {
    float2 f;
    asm("mov.b64 {%0, %1}, %2;" : "=f"(f.x), "=f"(f.y) : "l"(v));
    return f;
}

// ---- fast activations (MUFU EX2/RCP, proven ~2.5e-7 end-to-end) ----
__device__ __forceinline__ float fast_ex2(float x) {
    float y; asm("ex2.approx.f32 %0, %1;" : "=f"(y) : "f"(x)); return y;
}
__device__ __forceinline__ float fast_rcp(float x) {
    float y; asm("rcp.approx.f32 %0, %1;" : "=f"(y) : "f"(x)); return y;
}
__device__ __forceinline__ float sigf(float x) {
    return fast_rcp(1.0f + fast_ex2(-1.4426950408889634f * x));
}
__device__ __forceinline__ float tanhf_fast(float x) {
    x = fminf(fmaxf(x, -15.0f), 15.0f);
    float e = fast_ex2(-2.8853900817779268f * x);  // exp(-2x)
    return (1.0f - e) * fast_rcp(1.0f + e);
}

// k-pair GEMM fragment: per k2 (2 k's): 2 LDS.128 acts + 4 x.128 weights + 32 FFMA2.
// acc[r][q]: f32x2 (even-k, odd-k) partials; q = gate*2 + cellpar; row m0+r. ZERO MOVs.
template <bool GW, bool FIRST, int K2N>
__device__ __forceinline__ void gemm_kp(const float* __restrict__ aT,
                                        const float* __restrict__ Wq,
                                        int aoff, int gn4, u64 acc[4][8])
{
#pragma unroll 2
    for (int k2 = 0; k2 < K2N; k2++) {
        ulonglong2 a01 = *(const ulonglong2*)(aT + k2 * STK + aoff);
        ulonglong2 a23 = *(const ulonglong2*)(aT + k2 * STK + aoff + 4);
        u64 w[8];
#pragma unroll
        for (int j = 0; j < 4; j++) {
            const float* wp = Wq + k2 * WR + j * 128 + gn4;
            ulonglong2 wv;
            if (GW) wv = __ldg((const ulonglong2*)wp);
            else    wv = *(const ulonglong2*)wp;
            w[2 * j] = wv.x; w[2 * j + 1] = wv.y;
        }
        if (FIRST && k2 == 0) {
#pragma unroll
            for (int q = 0; q < 8; q++) {
                acc[0][q] = mul2(a01.x, w[q]);
                acc[1][q] = mul2(a01.y, w[q]);
                acc[2][q] = mul2(a23.x, w[q]);
                acc[3][q] = mul2(a23.y, w[q]);
            }
        } else {
#pragma unroll
            for (int q = 0; q < 8; q++) acc[0][q] = fma2(a01.x, w[q], acc[0][q]);
#pragma unroll
            for (int q = 0; q < 8; q++) acc[1][q] = fma2(a01.y, w[q], acc[1][q]);
#pragma unroll
            for (int q = 0; q < 8; q++) acc[2][q] = fma2(a23.x, w[q], acc[2][q]);
#pragma unroll
            for (int q = 0; q < 8; q++) acc[3][q] = fma2(a23.y, w[q], acc[3][q]);
        }
    }
}

// fold even/odd-k partials + bias, gates, cell update, store h pairs (2 STS.128)
__device__ __forceinline__ void lstm_update_kp(const u64 acc[4][8],
                                               const float* __restrict__ bq,
                                               float c[4][2], float* __restrict__ dst,
                                               int aoff)
{
    float4 bl0 = *(const float4*)bq;
    float4 bl1 = *(const float4*)(bq + 4);
    float b[8] = {bl0.x, bl0.y, bl0.z, bl0.w, bl1.x, bl1.y, bl1.z, bl1.w};
    float h[4][2];
#pragma unroll
    for (int r = 0; r < 4; r++) {
#pragma unroll
        for (int cp = 0; cp < 2; cp++) {
            float2 pi = unpack2(acc[r][0 + cp]);
            float2 pf = unpack2(acc[r][2 + cp]);
            float2 pg = unpack2(acc[r][4 + cp]);
            float2 po = unpack2(acc[r][6 + cp]);
            float iv = sigf(pi.x + pi.y + b[0 + cp]);
            float fv = sigf(pf.x + pf.y + b[2 + cp]);
            float gv = tanhf_fast(pg.x + pg.y + b[4 + cp]);
            float ov = sigf(po.x + po.y + b[6 + cp]);
            float cc = fv * c[r][cp] + iv * gv;
            c[r][cp] = cc;
            h[r][cp] = ov * tanhf_fast(cc);
        }
    }
    *(float4*)(dst + aoff)     = make_float4(h[0][0], h[0][1], h[1][0], h[1][1]);
    *(float4*)(dst + aoff + 4) = make_float4(h[2][0], h[2][1], h[3][0], h[3][1]);
}

// Shared layout (floats)
#define OFF_W0   0                           // Whh0: 16384
#define OFF_W1   (OFF_W0 + 32 * WR)          // Wih1+Whh1: 32768
#define OFF_B0   (OFF_W1 + 64 * WR)          // 256
#define OFF_B1   (OFF_B0 + 256)              // 256
#define OFF_H0   (OFF_B1 + 256)              // 32*68
#define OFF_H1   (OFF_H0 + 32 * STK)
#define OFF_X    (OFF_H1 + 32 * STK)         // 16*68
#define SMEM_FLOATS (OFF_X + 16 * STK)       // 55104 floats = 220416 B

__global__ void __launch_bounds__(NTHR, 1)
lstm_fused(const float* __restrict__ x,
           const float* __restrict__ W1h, const float* __restrict__ b1h,
           const float* __restrict__ W2h, const float* __restrict__ b2h,
           float* __restrict__ out)
{
    extern __shared__ float sm[];
    float* sW0 = sm + OFF_W0;
    float* sW1 = sm + OFF_W1;
    float* sB0 = sm + OFF_B0;
    float* sB1 = sm + OFF_B1;
    float* h0T = sm + OFF_H0;
    float* h1T = sm + OFF_H1;
    float* xT  = sm + OFF_X;

    const int tid = threadIdx.x;
    const int b0  = blockIdx.x * BT;

    // stage weights + biases; zero act buffers (h0T,h1T,xT contiguous)
    for (int i = tid; i < 32 * WR / 4; i += NTHR)
        ((float4*)sW0)[i] = ((const float4*)g_W0p)[i];
    for (int i = tid; i < 64 * WR / 4; i += NTHR)
        ((float4*)sW1)[i] = ((const float4*)g_W1p)[i];
    if (tid < 64)            ((float4*)sB0)[tid]      = ((const float4*)g_b0p)[tid];
    else if (tid < 128)      ((float4*)sB1)[tid - 64] = ((const float4*)g_b1p)[tid - 64];
    for (int i = tid; i < 80 * STK; i += NTHR) h0T[i] = 0.0f;

    // thread tile: rows m0..m0+3 (gm), cells u0=gn*2, u0+1
    const int gm = tid & 7;
    const int gn = tid >> 3;                       // 0..31
    const int aoff = gm * 8 + (gm >= 4 ? 4 : 0);   // skewed act offset (conflict-free)
    const int gn4 = gn * 4;                        // float offset within a j-plane

    float c0[4][2] = {{0,0},{0,0},{0,0},{0,0}};
    float c1[4][2] = {{0,0},{0,0},{0,0},{0,0}};
    u64 acc0[4][8], acc1[4][8];

    // x staging: thread -> (row xm, float4 chunk xd); stored as k-pairs
    const int xm = tid >> 3;
    const int xd = tid & 7;
    const int axm = (xm >> 2) * 8 + ((xm >> 2) >= 4 ? 4 : 0) + (xm & 3) * 2;
    const float* xptr = x + (size_t)(b0 + xm) * SEQT * DIN + xd * 4;

    // prologue: stage x(0); acc0 = Wih0*x(0) (FIRST; h0(-1)=0 so Whh0 term skipped)
    float4 xv = *(const float4*)(xptr);
    *(float2*)(xT + (2 * xd + 0) * STK + axm) = make_float2(xv.x, xv.y);
    *(float2*)(xT + (2 * xd + 1) * STK + axm) = make_float2(xv.z, xv.w);
    __syncthreads();

    gemm_kp<true, true, 16>(xT, g_Wx0p, aoff, gn4, acc0);
    xv = *(const float4*)(xptr + DIN);      // x(1)
    __syncthreads();                        // xT readers done before loop restage

    for (int t = 0; t < SEQT; t++) {
        // ---- P1: update0(t) (MUFU) || Whh1*h1(t-1) (FFMA, FIRST) + stage x(t+1)
        lstm_update_kp(acc0, sB0 + gn * 8, c0, h0T + gn * STK, aoff);  // writes h0(t)
        gemm_kp<false, true, 32>(h1T, sW1 + 32 * WR, aoff, gn4, acc1); // Whh1*h1(t-1)
        *(float2*)(xT + (2 * xd + 0) * STK + axm) = make_float2(xv.x, xv.y);
        *(float2*)(xT + (2 * xd + 1) * STK + axm) = make_float2(xv.z, xv.w);
        {
            int tn = (t + 2 < SEQT) ? t + 2 : SEQT - 1;
            xv = *(const float4*)(xptr + (size_t)tn * DIN);   // prefetch x(t+2)
        }
        __syncthreads();                                      // B1: h0(t), x(t+1) visible

        // ---- P2/P3: Wih1*h0(t); gemm0(t+1); update1(t) (MUFU overlaps FFMA tail)
        gemm_kp<false, false, 32>(h0T, sW1, aoff, gn4, acc1);             // Wih1*h0(t)
        if (t + 1 < SEQT) {
            gemm_kp<false, true, 16>(h0T, sW0, aoff, gn4, acc0);          // Whh0 k2 0..15 (FIRST)
            gemm_kp<true, false, 16>(xT, g_Wx0p, aoff, gn4, acc0);        // Wih0*x(t+1)
            gemm_kp<false, false, 16>(h0T + 16 * STK, sW0 + 16 * WR, aoff, gn4, acc0); // Whh0 16..31
        }
        lstm_update_kp(acc1, sB1 + gn * 8, c1, h1T + gn * STK, aoff);     // writes h1(t)
        __syncthreads();                                      // B2: h1(t) visible
    }

    // ---- head: out[m] = b2 + sum_n W2[n]*relu(b1[n] + sum_k h1(k,m) W1[n,k]) ----
    {
        int m = tid >> 3;      // 0..31
        int q = tid & 7;       // 0..7
        int mb = (m >> 2) * 8 + ((m >> 2) >= 4 ? 4 : 0) + (m & 3) * 2;
        float pm = 0.0f;
#pragma unroll
        for (int jj = 0; jj < 8; jj++) {
            int n = q * 8 + jj;
            float s = b1h[n];
#pragma unroll 8
            for (int k = 0; k < HID; k++)
                s += h1T[(k >> 1) * STK + mb + (k & 1)] * W1h[n * HID + k];
            pm += fmaxf(s, 0.0f) * W2h[n];
        }
#pragma unroll
        for (int off = 4; off > 0; off >>= 1)
            pm += __shfl_down_sync(0xffffffffu, pm, off, 8);
        if (q == 0) out[b0 + m] = pm + b2h[0];
    }
}

extern "C" void kernel_launch(void* const* d_in, const int* in_sizes, int n_in,
                              void* d_out, int out_size)
{
    const float* x    = (const float*)d_in[0];
    const float* Wih0 = (const float*)d_in[1];
    const float* Whh0 = (const float*)d_in[2];
    const float* bih0 = (const float*)d_in[3];
    const float* bhh0 = (const float*)d_in[4];
    const float* Wih1 = (const float*)d_in[5];
    const float* Whh1 = (const float*)d_in[6];
    const float* bih1 = (const float*)d_in[7];
    const float* bhh1 = (const float*)d_in[8];
    const float* W1   = (const float*)d_in[9];
    const float* b1   = (const float*)d_in[10];
    const float* W2   = (const float*)d_in[11];
    const float* b2   = (const float*)d_in[12];

    prep_kernel<<<64, 256>>>(Wih0, Whh0, bih0, bhh0, Wih1, Whh1, bih1, bhh1);

    size_t smem_bytes = (size_t)SMEM_FLOATS * sizeof(float);  // 220416 B
    cudaFuncSetAttribute(lstm_fused,
                         cudaFuncAttributeMaxDynamicSharedMemorySize, (int)smem_bytes);
    lstm_fused<<<NCTA, NTHR, smem_bytes>>>(x, W1, b1, W2, b2, (float*)d_out);
}

// round 16
// speedup vs baseline: 1.3303x; 1.3303x over previous
#include <cuda_runtime.h>

#define BATCH 4096
#define SEQT  256
#define DIN   32
#define HID   64
#define GATES 256
#define BT    32
#define NTHR  256
#define NCTA  128
#define ST    36    // padded row stride (floats) for transposed activation buffers

typedef unsigned long long u64;

// ---- gate-quad weight layout W[k][u2][g][upar]: n = g*64 + u2*2 + up (R14-proven) ----
__device__ __align__(16) float g_W0q[HID * GATES];     // Whh0 quad [64][256]
__device__ __align__(16) float g_Wx0q[DIN * GATES];    // Wih0 quad [32][256] (per-step LDG)
__device__ __align__(16) float g_W1q[2 * HID * GATES]; // [Wih1; Whh1] quad [128][256]
__device__ __align__(16) float g_b0q[GATES];
__device__ __align__(16) float g_b1q[GATES];

__global__ void prep_kernel(const float* __restrict__ Wih0, const float* __restrict__ Whh0,
                            const float* __restrict__ bih0, const float* __restrict__ bhh0,
                            const float* __restrict__ Wih1, const float* __restrict__ Whh1,
                            const float* __restrict__ bih1, const float* __restrict__ bhh1)
{
    int idx = blockIdx.x * blockDim.x + threadIdx.x;
    int stride = gridDim.x * blockDim.x;
    for (int j = idx; j < HID * GATES; j += stride) {
        int k = j / GATES, r = j % GATES;
        int n = ((r >> 1) & 3) * HID + (r >> 3) * 2 + (r & 1);
        g_W0q[j] = Whh0[n * HID + k];
    }
    for (int j = idx; j < DIN * GATES; j += stride) {
        int k = j / GATES, r = j % GATES;
        int n = ((r >> 1) & 3) * HID + (r >> 3) * 2 + (r & 1);
        g_Wx0q[j] = Wih0[n * DIN + k];
    }
    for (int j = idx; j < 2 * HID * GATES; j += stride) {
        int k = j / GATES, r = j % GATES;
        int n = ((r >> 1) & 3) * HID + (r >> 3) * 2 + (r & 1);
        g_W1q[j] = (k < HID) ? Wih1[n * HID + k] : Whh1[n * HID + (k - HID)];
    }
    for (int r = idx; r < GATES; r += stride) {
        int n = ((r >> 1) & 3) * HID + (r >> 3) * 2 + (r & 1);
        g_b0q[r] = bih0[n] + bhh0[n];
        g_b1q[r] = bih1[n] + bhh1[n];
    }
}

// ---- packed f32x2 helpers ----
__device__ __forceinline__ u64 fma2(u64 a, u64 b, u64 c) {
    u64 d;
    asm("fma.rn.f32x2 %0, %1, %2, %3;" : "=l"(d) : "l"(a), "l"(b), "l"(c));
    return d;
}
__device__ __forceinline__ u64 dup2(float x) {
    u64 d;
    asm("mov.b64 %0, {%1, %1};" : "=l"(d) : "f"(x));
    return d;
}
__device__ __forceinline__ float2 unpack2(u64 v) {
    float2 f;
    asm("mov.b64 {%0, %1}, %2;" : "=f"(f.x), "=f"(f.y) : "l"(v));
    return f;
}

// ---- fast activations (MUFU EX2/RCP, proven ~2.5e-7 end-to-end) ----
__device__ __forceinline__ float fast_ex2(float x) {
    float y; asm("ex2.approx.f32 %0, %1;" : "=f"(y) : "f"(x)); return y;
}
__device__ __forceinline__ float fast_rcp(float x) {
    float y; asm("rcp.approx.f32 %0, %1;" : "=f"(y) : "f"(x)); return y;
}
__device__ __forceinline__ float sigf(float x) {
    return fast_rcp(1.0f + fast_ex2(-1.4426950408889634f * x));
}
__device__ __forceinline__ float tanhf_fast(float x) {
    x = fminf(fmaxf(x, -15.0f), 15.0f);
    float e = fast_ex2(-2.8853900817779268f * x);  // exp(-2x)
    return (1.0f - e) * fast_rcp(1.0f + e);
}

// GEMM fragment, quad layout: per k: 1 LDS.128 act (4 rows) + 2 LDS.128 weights (8 cols),
// 4 dup2, 16 FFMA2. acc[r][g] = f32x2 over cells (u0,u0+1), gate g, row m0+r.
template <bool GW, int K>
__device__ __forceinline__ void gemm_q4(const float* __restrict__ aT,
                                        const float* __restrict__ Wq,
                                        int m0, int w8, u64 acc[4][4])
{
#pragma unroll 8
    for (int k = 0; k < K; k++) {
        float4 hv = *(const float4*)(aT + k * ST + m0);
        const float* wp = Wq + k * GATES + w8;
        ulonglong2 wv0, wv1;
        if (GW) {
            wv0 = __ldg((const ulonglong2*)wp);       // gates i,f (cells u0,u0+1)
            wv1 = __ldg((const ulonglong2*)(wp + 4)); // gates g,o
        } else {
            wv0 = *(const ulonglong2*)wp;
            wv1 = *(const ulonglong2*)(wp + 4);
        }
        u64 a;
        a = dup2(hv.x);
        acc[0][0] = fma2(a, wv0.x, acc[0][0]);
        acc[0][1] = fma2(a, wv0.y, acc[0][1]);
        acc[0][2] = fma2(a, wv1.x, acc[0][2]);
        acc[0][3] = fma2(a, wv1.y, acc[0][3]);
        a = dup2(hv.y);
        acc[1][0] = fma2(a, wv0.x, acc[1][0]);
        acc[1][1] = fma2(a, wv0.y, acc[1][1]);
        acc[1][2] = fma2(a, wv1.x, acc[1][2]);
        acc[1][3] = fma2(a, wv1.y, acc[1][3]);
        a = dup2(hv.z);
        acc[2][0] = fma2(a, wv0.x, acc[2][0]);
        acc[2][1] = fma2(a, wv0.y, acc[2][1]);
        acc[2][2] = fma2(a, wv1.x, acc[2][2]);
        acc[2][3] = fma2(a, wv1.y, acc[2][3]);
        a = dup2(hv.w);
        acc[3][0] = fma2(a, wv0.x, acc[3][0]);
        acc[3][1] = fma2(a, wv0.y, acc[3][1]);
        acc[3][2] = fma2(a, wv1.x, acc[3][2]);
        acc[3][3] = fma2(a, wv1.y, acc[3][3]);
    }
}

__device__ __forceinline__ void acc_init(const float* __restrict__ sB, int w8, u64 acc[4][4])
{
    ulonglong2 b0 = *(const ulonglong2*)(sB + w8);
    ulonglong2 b1 = *(const ulonglong2*)(sB + w8 + 4);
#pragma unroll
    for (int r = 0; r < 4; r++) {
        acc[r][0] = b0.x; acc[r][1] = b0.y; acc[r][2] = b1.x; acc[r][3] = b1.y;
    }
}

// activations + cell update + write h (transposed): 4 rows x 2 cells per thread
__device__ __forceinline__ void lstm_update(const u64 acc[4][4], float* __restrict__ cr,
                                            float* __restrict__ hT, int m0, int u0)
{
    float hn0[4], hn1[4];
#pragma unroll
    for (int m = 0; m < 4; m++) {
        float2 pi = unpack2(acc[m][0]);
        float2 pf = unpack2(acc[m][1]);
        float2 pg = unpack2(acc[m][2]);
        float2 po = unpack2(acc[m][3]);
        {
            float iv = sigf(pi.x), fv = sigf(pf.x), gv = tanhf_fast(pg.x), ov = sigf(po.x);
            float c = fv * cr[m * 2 + 0] + iv * gv;
            cr[m * 2 + 0] = c;
            hn0[m] = ov * tanhf_fast(c);
        }
        {
            float iv = sigf(pi.y), fv = sigf(pf.y), gv = tanhf_fast(pg.y), ov = sigf(po.y);
            float c = fv * cr[m * 2 + 1] + iv * gv;
            cr[m * 2 + 1] = c;
            hn1[m] = ov * tanhf_fast(c);
        }
    }
    *(float4*)(hT + (u0 + 0) * ST + m0) = make_float4(hn0[0], hn0[1], hn0[2], hn0[3]);
    *(float4*)(hT + (u0 + 1) * ST + m0) = make_float4(hn1[0], hn1[1], hn1[2], hn1[3]);
}

// Shared layout (floats) — identical footprint to R14 (221696 B)
#define OFF_W0   0
#define OFF_W1   (OFF_W0 + HID * GATES)
#define OFF_B0   (OFF_W1 + 2 * HID * GATES)
#define OFF_B1   (OFF_B0 + GATES)
#define OFF_H0T  (OFF_B1 + GATES)
#define OFF_H1T  (OFF_H0T + HID * ST)
#define OFF_XT   (OFF_H1T + HID * ST)
#define SMEM_FLOATS (OFF_XT + DIN * ST)

__global__ void __launch_bounds__(NTHR, 1)
lstm_fused(const float* __restrict__ x,
           const float* __restrict__ W1h, const float* __restrict__ b1h,
           const float* __restrict__ W2h, const float* __restrict__ b2h,
           float* __restrict__ out)
{
    extern __shared__ float sm[];
    float* sW0 = sm + OFF_W0;              // Whh0 quad
    float* sW1 = sm + OFF_W1;              // [Wih1;Whh1] quad
    float* sB0 = sm + OFF_B0;
    float* sB1 = sm + OFF_B1;
    float* h0T = sm + OFF_H0T;
    float* h1T = sm + OFF_H1T;
    float* xT  = sm + OFF_XT;

    const int tid = threadIdx.x;
    const int b0  = blockIdx.x * BT;

    // stage weights + zero states
    for (int i = tid; i < HID * GATES / 4; i += NTHR)
        ((float4*)sW0)[i] = ((const float4*)g_W0q)[i];
    for (int i = tid; i < 2 * HID * GATES / 4; i += NTHR)
        ((float4*)sW1)[i] = ((const float4*)g_W1q)[i];
    if (tid < GATES) { sB0[tid] = g_b0q[tid]; sB1[tid] = g_b1q[tid]; }
    for (int i = tid; i < 2 * HID * ST; i += NTHR) h0T[i] = 0.0f;  // h0T+h1T contiguous

    // thread tile: rows m0..m0+3; cells u0,u0+1 (quad block w8)
    const int gm = tid & 7;
    const int gn = tid >> 3;
    const int m0 = gm * 4;
    const int u0 = gn * 2;
    const int w8 = gn * 8;

    float c0r[8], c1r[8];
#pragma unroll
    for (int i = 0; i < 8; i++) { c0r[i] = 0.0f; c1r[i] = 0.0f; }

    // x staging: thread -> (row xm, float4 chunk xd)
    const int xm = tid >> 3;
    const int xd = tid & 7;
    const float* xptr = x + (size_t)(b0 + xm) * SEQT * DIN + xd * 4;

    // prologue: stage x(0), acc0(0) = b0 + Wih0*x(0)  (h0(-1)=0)
    float4 xv = *(const float4*)(xptr);
    xT[(4 * xd + 0) * ST + xm] = xv.x;
    xT[(4 * xd + 1) * ST + xm] = xv.y;
    xT[(4 * xd + 2) * ST + xm] = xv.z;
    xT[(4 * xd + 3) * ST + xm] = xv.w;
    __syncthreads();

    u64 acc0[4][4], acc1[4][4];
    acc_init(sB0, w8, acc0);
    gemm_q4<true, DIN>(xT, g_Wx0q, m0, w8, acc0);
    xv = *(const float4*)(xptr + DIN);      // x(1)
    __syncthreads();                        // xT readers done before loop overwrites

    for (int t = 0; t < SEQT; t++) {
        // ---- P1a: update0(t) -> h0(t) stores; stage x(t+1); then ARRIVE (stores visible)
        lstm_update(acc0, c0r, h0T, m0, u0);            // writes h0(t)
        xT[(4 * xd + 0) * ST + xm] = xv.x;              // stage x(t+1)
        xT[(4 * xd + 1) * ST + xm] = xv.y;
        xT[(4 * xd + 2) * ST + xm] = xv.z;
        xT[(4 * xd + 3) * ST + xm] = xv.w;
        {
            int tn = (t + 2 < SEQT) ? t + 2 : SEQT - 1;
            xv = *(const float4*)(xptr + (size_t)tn * DIN);  // prefetch x(t+2)
        }
        asm volatile("bar.arrive 1, 512;" ::: "memory");     // producer arrive (256+256=512)

        // ---- P1b: Whh1*h1(t-1) — independent of h0(t)/x(t+1); fills the join window
        acc_init(sB1, w8, acc1);
        gemm_q4<false, HID>(h1T, sW1 + HID * GATES, m0, w8, acc1);  // Whh1*h1(t-1)

        asm volatile("bar.sync 1, 512;" ::: "memory");       // near-free: all arrived already

        // ---- P2: Wih1*h0(t) + Whh0[0:32]*h0(t) + Wih0*x(t+1)  (pure FFMA)
        gemm_q4<false, HID>(h0T, sW1, m0, w8, acc1);    // Wih1*h0(t)
        acc_init(sB0, w8, acc0);
        gemm_q4<false, 32>(h0T, sW0, m0, w8, acc0);     // Whh0[k:0..31]
        gemm_q4<true, DIN>(xT, g_Wx0q, m0, w8, acc0);   // Wih0*x(t+1)

        // ---- P3 (no barrier): Whh0[32:64] (FFMA) || update1(t) (MUFU)
        gemm_q4<false, 32>(h0T + 32 * ST, sW0 + 32 * GATES, m0, w8, acc0); // Whh0[k:32..63]
        lstm_update(acc1, c1r, h1T, m0, u0);            // writes h1(t)
        __syncthreads();                                // B2: full join (protects h0/x overwrite
                                                        //     and h1(t) -> next-step readers)
    }

    // ---- head: out[m] = b2 + sum_n W2[n]*relu(b1[n] + sum_k h1(k,m) W1[n,k]) ----
    {
        int m = tid >> 3;      // 0..31
        int q = tid & 7;       // 0..7
        float pm = 0.0f;
#pragma unroll
        for (int jj = 0; jj < 8; jj++) {
            int n = q * 8 + jj;
            float s = b1h[n];
#pragma unroll 8
            for (int k = 0; k < HID; k++)
                s += h1T[k * ST + m] * W1h[n * HID + k];
            pm += fmaxf(s, 0.0f) * W2h[n];
        }
#pragma unroll
        for (int off = 4; off > 0; off >>= 1)
            pm += __shfl_down_sync(0xffffffffu, pm, off, 8);
        if (q == 0) out[b0 + m] = pm + b2h[0];
    }
}

extern "C" void kernel_launch(void* const* d_in, const int* in_sizes, int n_in,
                              void* d_out, int out_size)
{
    const float* x    = (const float*)d_in[0];
    const float* Wih0 = (const float*)d_in[1];
    const float* Whh0 = (const float*)d_in[2];
    const float* bih0 = (const float*)d_in[3];
    const float* bhh0 = (const float*)d_in[4];
    const float* Wih1 = (const float*)d_in[5];
    const float* Whh1 = (const float*)d_in[6];
    const float* bih1 = (const float*)d_in[7];
    const float* bhh1 = (const float*)d_in[8];
    const float* W1   = (const float*)d_in[9];
    const float* b1   = (const float*)d_in[10];
    const float* W2   = (const float*)d_in[11];
    const float* b2   = (const float*)d_in[12];

    prep_kernel<<<64, 256>>>(Wih0, Whh0, bih0, bhh0, Wih1, Whh1, bih1, bhh1);

    size_t smem_bytes = (size_t)SMEM_FLOATS * sizeof(float);  // 221696 B
    cudaFuncSetAttribute(lstm_fused,
                         cudaFuncAttributeMaxDynamicSharedMemorySize, (int)smem_bytes);
    lstm_fused<<<NCTA, NTHR, smem_bytes>>>(x, W1, b1, W2, b2, (float*)d_out);
}

// round 17
// speedup vs baseline: 1.3327x; 1.0018x over previous
#include <cuda_runtime.h>

#define BATCH 4096
#define SEQT  256
#define DIN   32
#define HID   64
#define GATES 256
#define BT    32
#define NTHR  256
#define NCTA  128
#define ST    36    // padded row stride (floats) for transposed activation buffers

typedef unsigned long long u64;

// ---- gate-quad weight layout W[k][u2][g][upar]: n = g*64 + u2*2 + up (R14-proven) ----
__device__ __align__(16) float g_W0q[HID * GATES];     // Whh0 quad [64][256]
__device__ __align__(16) float g_Wx0q[DIN * GATES];    // Wih0 quad [32][256] (per-step LDG)
__device__ __align__(16) float g_W1q[2 * HID * GATES]; // [Wih1; Whh1] quad [128][256]
__device__ __align__(16) float g_b0q[GATES];
__device__ __align__(16) float g_b1q[GATES];

__global__ void prep_kernel(const float* __restrict__ Wih0, const float* __restrict__ Whh0,
                            const float* __restrict__ bih0, const float* __restrict__ bhh0,
                            const float* __restrict__ Wih1, const float* __restrict__ Whh1,
                            const float* __restrict__ bih1, const float* __restrict__ bhh1)
{
    int idx = blockIdx.x * blockDim.x + threadIdx.x;
    int stride = gridDim.x * blockDim.x;
    for (int j = idx; j < HID * GATES; j += stride) {
        int k = j / GATES, r = j % GATES;
        int n = ((r >> 1) & 3) * HID + (r >> 3) * 2 + (r & 1);
        g_W0q[j] = Whh0[n * HID + k];
    }
    for (int j = idx; j < DIN * GATES; j += stride) {
        int k = j / GATES, r = j % GATES;
        int n = ((r >> 1) & 3) * HID + (r >> 3) * 2 + (r & 1);
        g_Wx0q[j] = Wih0[n * DIN + k];
    }
    for (int j = idx; j < 2 * HID * GATES; j += stride) {
        int k = j / GATES, r = j % GATES;
        int n = ((r >> 1) & 3) * HID + (r >> 3) * 2 + (r & 1);
        g_W1q[j] = (k < HID) ? Wih1[n * HID + k] : Whh1[n * HID + (k - HID)];
    }
    for (int r = idx; r < GATES; r += stride) {
        int n = ((r >> 1) & 3) * HID + (r >> 3) * 2 + (r & 1);
        g_b0q[r] = bih0[n] + bhh0[n];
        g_b1q[r] = bih1[n] + bhh1[n];
    }
}

// ---- packed f32x2 helpers ----
__device__ __forceinline__ u64 fma2(u64 a, u64 b, u64 c) {
    u64 d;
    asm("fma.rn.f32x2 %0, %1, %2, %3;" : "=l"(d) : "l"(a), "l"(b), "l"(c));
    return d;
}
__device__ __forceinline__ u64 dup2(float x) {
    u64 d;
    asm("mov.b64 %0, {%1, %1};" : "=l"(d) : "f"(x));
    return d;
}
__device__ __forceinline__ float2 unpack2(u64 v) {
    float2 f;
    asm("mov.b64 {%0, %1}, %2;" : "=f"(f.x), "=f"(f.y) : "l"(v));
    return f;
}

// ---- fast activations (MUFU EX2/RCP, proven ~2.5e-7 end-to-end) ----
__device__ __forceinline__ float fast_ex2(float x) {
    float y; asm("ex2.approx.f32 %0, %1;" : "=f"(y) : "f"(x)); return y;
}
__device__ __forceinline__ float fast_rcp(float x) {
    float y; asm("rcp.approx.f32 %0, %1;" : "=f"(y) : "f"(x)); return y;
}
__device__ __forceinline__ float sigf(float x) {
    return fast_rcp(1.0f + fast_ex2(-1.4426950408889634f * x));
}
__device__ __forceinline__ float tanhf_fast(float x) {
    x = fminf(fmaxf(x, -15.0f), 15.0f);
    float e = fast_ex2(-2.8853900817779268f * x);  // exp(-2x)
    return (1.0f - e) * fast_rcp(1.0f + e);
}

// GEMM fragment, quad layout: per k: 1 LDS.128 act (4 rows) + 2 LDS.128 weights (8 cols),
// 4 dup2, 16 FFMA2. acc[r][g] = f32x2 over cells (u0,u0+1), gate g, row m0+r.
template <bool GW, int K>
__device__ __forceinline__ void gemm_q4(const float* __restrict__ aT,
                                        const float* __restrict__ Wq,
                                        int m0, int w8, u64 acc[4][4])
{
#pragma unroll 8
    for (int k = 0; k < K; k++) {
        float4 hv = *(const float4*)(aT + k * ST + m0);
        const float* wp = Wq + k * GATES + w8;
        ulonglong2 wv0, wv1;
        if (GW) {
            wv0 = __ldg((const ulonglong2*)wp);       // gates i,f (cells u0,u0+1)
            wv1 = __ldg((const ulonglong2*)(wp + 4)); // gates g,o
        } else {
            wv0 = *(const ulonglong2*)wp;
            wv1 = *(const ulonglong2*)(wp + 4);
        }
        u64 a;
        a = dup2(hv.x);
        acc[0][0] = fma2(a, wv0.x, acc[0][0]);
        acc[0][1] = fma2(a, wv0.y, acc[0][1]);
        acc[0][2] = fma2(a, wv1.x, acc[0][2]);
        acc[0][3] = fma2(a, wv1.y, acc[0][3]);
        a = dup2(hv.y);
        acc[1][0] = fma2(a, wv0.x, acc[1][0]);
        acc[1][1] = fma2(a, wv0.y, acc[1][1]);
        acc[1][2] = fma2(a, wv1.x, acc[1][2]);
        acc[1][3] = fma2(a, wv1.y, acc[1][3]);
        a = dup2(hv.z);
        acc[2][0] = fma2(a, wv0.x, acc[2][0]);
        acc[2][1] = fma2(a, wv0.y, acc[2][1]);
        acc[2][2] = fma2(a, wv1.x, acc[2][2]);
        acc[2][3] = fma2(a, wv1.y, acc[2][3]);
        a = dup2(hv.w);
        acc[3][0] = fma2(a, wv0.x, acc[3][0]);
        acc[3][1] = fma2(a, wv0.y, acc[3][1]);
        acc[3][2] = fma2(a, wv1.x, acc[3][2]);
        acc[3][3] = fma2(a, wv1.y, acc[3][3]);
    }
}

__device__ __forceinline__ void acc_init(const float* __restrict__ sB, int w8, u64 acc[4][4])
{
    ulonglong2 b0 = *(const ulonglong2*)(sB + w8);
    ulonglong2 b1 = *(const ulonglong2*)(sB + w8 + 4);
#pragma unroll
    for (int r = 0; r < 4; r++) {
        acc[r][0] = b0.x; acc[r][1] = b0.y; acc[r][2] = b1.x; acc[r][3] = b1.y;
    }
}

// activations + cell update + write h (transposed): 4 rows x 2 cells per thread
__device__ __forceinline__ void lstm_update(const u64 acc[4][4], float* __restrict__ cr,
                                            float* __restrict__ hT, int m0, int u0)
{
    float hn0[4], hn1[4];
#pragma unroll
    for (int m = 0; m < 4; m++) {
        float2 pi = unpack2(acc[m][0]);
        float2 pf = unpack2(acc[m][1]);
        float2 pg = unpack2(acc[m][2]);
        float2 po = unpack2(acc[m][3]);
        {
            float iv = sigf(pi.x), fv = sigf(pf.x), gv = tanhf_fast(pg.x), ov = sigf(po.x);
            float c = fv * cr[m * 2 + 0] + iv * gv;
            cr[m * 2 + 0] = c;
            hn0[m] = ov * tanhf_fast(c);
        }
        {
            float iv = sigf(pi.y), fv = sigf(pf.y), gv = tanhf_fast(pg.y), ov = sigf(po.y);
            float c = fv * cr[m * 2 + 1] + iv * gv;
            cr[m * 2 + 1] = c;
            hn1[m] = ov * tanhf_fast(c);
        }
    }
    *(float4*)(hT + (u0 + 0) * ST + m0) = make_float4(hn0[0], hn0[1], hn0[2], hn0[3]);
    *(float4*)(hT + (u0 + 1) * ST + m0) = make_float4(hn1[0], hn1[1], hn1[2], hn1[3]);
}

// Shared layout (floats) — identical footprint to R14 (221696 B)
#define OFF_W0   0
#define OFF_W1   (OFF_W0 + HID * GATES)
#define OFF_B0   (OFF_W1 + 2 * HID * GATES)
#define OFF_B1   (OFF_B0 + GATES)
#define OFF_H0T  (OFF_B1 + GATES)
#define OFF_H1T  (OFF_H0T + HID * ST)
#define OFF_XT   (OFF_H1T + HID * ST)
#define SMEM_FLOATS (OFF_XT + DIN * ST)

__global__ void __launch_bounds__(NTHR, 1)
lstm_fused(const float* __restrict__ x,
           const float* __restrict__ W1h, const float* __restrict__ b1h,
           const float* __restrict__ W2h, const float* __restrict__ b2h,
           float* __restrict__ out)
{
    extern __shared__ float sm[];
    float* sW0 = sm + OFF_W0;              // Whh0 quad
    float* sW1 = sm + OFF_W1;              // [Wih1;Whh1] quad
    float* sB0 = sm + OFF_B0;
    float* sB1 = sm + OFF_B1;
    float* h0T = sm + OFF_H0T;
    float* h1T = sm + OFF_H1T;
    float* xT  = sm + OFF_XT;

    const int tid = threadIdx.x;
    const int b0  = blockIdx.x * BT;

    // stage weights + zero states
    for (int i = tid; i < HID * GATES / 4; i += NTHR)
        ((float4*)sW0)[i] = ((const float4*)g_W0q)[i];
    for (int i = tid; i < 2 * HID * GATES / 4; i += NTHR)
        ((float4*)sW1)[i] = ((const float4*)g_W1q)[i];
    if (tid < GATES) { sB0[tid] = g_b0q[tid]; sB1[tid] = g_b1q[tid]; }
    for (int i = tid; i < 2 * HID * ST; i += NTHR) h0T[i] = 0.0f;  // h0T+h1T contiguous

    // thread tile: rows m0..m0+3; cells u0,u0+1 (quad block w8)
    const int gm = tid & 7;
    const int gn = tid >> 3;
    const int m0 = gm * 4;
    const int u0 = gn * 2;
    const int w8 = gn * 8;

    float c0r[8], c1r[8];
#pragma unroll
    for (int i = 0; i < 8; i++) { c0r[i] = 0.0f; c1r[i] = 0.0f; }

    // x staging: thread -> (row xm, float4 chunk xd)
    const int xm = tid >> 3;
    const int xd = tid & 7;
    const float* xptr = x + (size_t)(b0 + xm) * SEQT * DIN + xd * 4;

    // prologue: stage x(0), acc0(0) = b0 + Wih0*x(0)  (h0(-1)=0)
    float4 xv = *(const float4*)(xptr);
    xT[(4 * xd + 0) * ST + xm] = xv.x;
    xT[(4 * xd + 1) * ST + xm] = xv.y;
    xT[(4 * xd + 2) * ST + xm] = xv.z;
    xT[(4 * xd + 3) * ST + xm] = xv.w;
    __syncthreads();

    u64 acc0[4][4], acc1[4][4];
    acc_init(sB0, w8, acc0);
    gemm_q4<true, DIN>(xT, g_Wx0q, m0, w8, acc0);
    xv = *(const float4*)(xptr + DIN);      // x(1)
    __syncthreads();                        // xT readers done before loop overwrites

    for (int t = 0; t < SEQT; t++) {
        // ---- P1a: update0(t) -> h0(t) stores; stage x(t+1); then ARRIVE (stores visible)
        lstm_update(acc0, c0r, h0T, m0, u0);            // writes h0(t)
        xT[(4 * xd + 0) * ST + xm] = xv.x;              // stage x(t+1)
        xT[(4 * xd + 1) * ST + xm] = xv.y;
        xT[(4 * xd + 2) * ST + xm] = xv.z;
        xT[(4 * xd + 3) * ST + xm] = xv.w;
        {
            int tn = (t + 2 < SEQT) ? t + 2 : SEQT - 1;
            xv = *(const float4*)(xptr + (size_t)tn * DIN);  // prefetch x(t+2)
        }
        asm volatile("bar.arrive 1, 512;" ::: "memory");     // producer arrive (256+256=512)

        // ---- P1b: Whh1*h1(t-1) — independent of h0(t)/x(t+1); fills the join window
        acc_init(sB1, w8, acc1);
        gemm_q4<false, HID>(h1T, sW1 + HID * GATES, m0, w8, acc1);  // Whh1*h1(t-1)

        asm volatile("bar.sync 1, 512;" ::: "memory");       // near-free: all arrived already

        // ---- P2: Wih1*h0(t) + Whh0[0:32]*h0(t) + Wih0*x(t+1)  (pure FFMA)
        gemm_q4<false, HID>(h0T, sW1, m0, w8, acc1);    // Wih1*h0(t)
        acc_init(sB0, w8, acc0);
        gemm_q4<false, 32>(h0T, sW0, m0, w8, acc0);     // Whh0[k:0..31]
        gemm_q4<true, DIN>(xT, g_Wx0q, m0, w8, acc0);   // Wih0*x(t+1)

        // ---- P3 (no barrier): Whh0[32:64] (FFMA) || update1(t) (MUFU)
        gemm_q4<false, 32>(h0T + 32 * ST, sW0 + 32 * GATES, m0, w8, acc0); // Whh0[k:32..63]
        lstm_update(acc1, c1r, h1T, m0, u0);            // writes h1(t)
        __syncthreads();                                // B2: full join (protects h0/x overwrite
                                                        //     and h1(t) -> next-step readers)
    }

    // ---- head: out[m] = b2 + sum_n W2[n]*relu(b1[n] + sum_k h1(k,m) W1[n,k]) ----
    {
        int m = tid >> 3;      // 0..31
        int q = tid & 7;       // 0..7
        float pm = 0.0f;
#pragma unroll
        for (int jj = 0; jj < 8; jj++) {
            int n = q * 8 + jj;
            float s = b1h[n];
#pragma unroll 8
            for (int k = 0; k < HID; k++)
                s += h1T[k * ST + m] * W1h[n * HID + k];
            pm += fmaxf(s, 0.0f) * W2h[n];
        }
#pragma unroll
        for (int off = 4; off > 0; off >>= 1)
            pm += __shfl_down_sync(0xffffffffu, pm, off, 8);
        if (q == 0) out[b0 + m] = pm + b2h[0];
    }
}

extern "C" void kernel_launch(void* const* d_in, const int* in_sizes, int n_in,
                              void* d_out, int out_size)
{
    const float* x    = (const float*)d_in[0];
    const float* Wih0 = (const float*)d_in[1];
    const float* Whh0 = (const float*)d_in[2];
    const float* bih0 = (const float*)d_in[3];
    const float* bhh0 = (const float*)d_in[4];
    const float* Wih1 = (const float*)d_in[5];
    const float* Whh1 = (const float*)d_in[6];
    const float* bih1 = (const float*)d_in[7];
    const float* bhh1 = (const float*)d_in[8];
    const float* W1   = (const float*)d_in[9];
    const float* b1   = (const float*)d_in[10];
    const float* W2   = (const float*)d_in[11];
    const float* b2   = (const float*)d_in[12];

    prep_kernel<<<64, 256>>>(Wih0, Whh0, bih0, bhh0, Wih1, Whh1, bih1, bhh1);

    size_t smem_bytes = (size_t)SMEM_FLOATS * sizeof(float);  // 221696 B
    cudaFuncSetAttribute(lstm_fused,
                         cudaFuncAttributeMaxDynamicSharedMemorySize, (int)smem_bytes);
    lstm_fused<<<NCTA, NTHR, smem_bytes>>>(x, W1, b1, W2, b2, (float*)d_out);
}